// round 9
// baseline (speedup 1.0000x reference)
#include <cuda_runtime.h>
#include <cuda_bf16.h>
#include <cuda_fp16.h>
#include <cstdint>
#include <cstddef>

// Problem constants
#define BB    8
#define SQ    4096
#define QD    1280
#define SCTX  93
#define CD    2048
#define NH    20
#define DH    64
#define INNER 1280

// ---------------------------------------------------------------------------
// Scratch (__device__ globals; no allocs allowed)
// ---------------------------------------------------------------------------
__device__ __align__(16) unsigned char g_qt[(size_t)BB * NH * 32 * 16384];
__device__ __align__(16) unsigned char g_kt[(size_t)BB * NH * 12288];
__device__ __align__(16) unsigned char g_vt[(size_t)BB * NH * 13312];

__device__ __half g_x16 [(size_t)BB * SQ * QD];
__device__ __half g_a16 [(size_t)BB * SQ * INNER];
__device__ __half g_wq16[(size_t)INNER * QD];
__device__ __half g_wo16[(size_t)QD * INNER];
__device__ float  g_k[(size_t)BB * NH * SCTX * DH];
__device__ float  g_v[(size_t)BB * NH * SCTX * DH];

// ---------------------------------------------------------------------------
// Helpers (arch-agnostic PTX only: cp.async, ldmatrix, mma.sync)
// ---------------------------------------------------------------------------
__device__ __forceinline__ uint32_t smem_u32(const void* p) {
    uint32_t a;
    asm("{ .reg .u64 t; cvta.to.shared.u64 t, %1; cvt.u32.u64 %0, t; }"
        : "=r"(a) : "l"(p));
    return a;
}
#define CP_COMMIT() asm volatile("cp.async.commit_group;" ::: "memory")
#define CP_WAIT(n)  asm volatile("cp.async.wait_group %0;" :: "n"(n) : "memory")
#define CP_ASYNC16(dst, src) \
    asm volatile("cp.async.cg.shared.global [%0], [%1], 16;" \
                 :: "r"(dst), "l"(src) : "memory")

__device__ __forceinline__ void ldsm_x4(uint32_t addr, uint32_t& r0, uint32_t& r1,
                                        uint32_t& r2, uint32_t& r3) {
    asm volatile("ldmatrix.sync.aligned.m8n8.x4.shared.b16 {%0,%1,%2,%3}, [%4];"
                 : "=r"(r0), "=r"(r1), "=r"(r2), "=r"(r3) : "r"(addr));
}
__device__ __forceinline__ void mma_fp16(float* c, const uint32_t* a,
                                         const uint32_t* b) {
    asm volatile(
        "mma.sync.aligned.m16n8k16.row.col.f32.f16.f16.f32 "
        "{%0,%1,%2,%3}, {%4,%5,%6,%7}, {%8,%9}, {%0,%1,%2,%3};"
        : "+f"(c[0]), "+f"(c[1]), "+f"(c[2]), "+f"(c[3])
        : "r"(a[0]), "r"(a[1]), "r"(a[2]), "r"(a[3]), "r"(b[0]), "r"(b[1]));
}
__device__ __forceinline__ uint32_t packhf(float x, float y) {
    __half2 t = __floats2half2_rn(x, y);
    return *(uint32_t*)&t;
}

// ---------------------------------------------------------------------------
// fp32 -> fp16 cast
// ---------------------------------------------------------------------------
__global__ void to_fp16(const float4* __restrict__ src,
                        ushort4* __restrict__ dst, int n4)
{
    for (int i = blockIdx.x * blockDim.x + threadIdx.x; i < n4;
         i += gridDim.x * blockDim.x) {
        float4 v = src[i];
        ushort4 o;
        o.x = __half_as_ushort(__float2half_rn(v.x));
        o.y = __half_as_ushort(__float2half_rn(v.y));
        o.z = __half_as_ushort(__float2half_rn(v.z));
        o.w = __half_as_ushort(__float2half_rn(v.w));
        dst[i] = o;
    }
}

// ---------------------------------------------------------------------------
// KV projections (fp32, small)
// ---------------------------------------------------------------------------
__global__ void __launch_bounds__(512) kv_proj_kernel(
    const float* __restrict__ ctx,
    const float* __restrict__ Wk,  const float* __restrict__ Wv,
    const float* __restrict__ Wki, const float* __restrict__ Wvi,
    const int*   __restrict__ nimg_p)
{
    __shared__ float cs[96][17];
    __shared__ float wk_s[64][17], wv_s[64][17], wki_s[64][17], wvi_s[64][17];

    const int tid = threadIdx.x;
    const int b   = blockIdx.y;
    const int hh  = blockIdx.x;
    const int n0  = hh * 64;
    const int eos = SCTX - *nimg_p;
    const int n   = tid & 63;
    const int g   = tid >> 6;

    float ak[12], av[12];
#pragma unroll
    for (int j = 0; j < 12; ++j) { ak[j] = 0.f; av[j] = 0.f; }

    for (int k0 = 0; k0 < CD; k0 += 16) {
        __syncthreads();
        for (int i = tid; i < 96 * 16; i += 512) {
            int s = i >> 4, kk = i & 15;
            cs[s][kk] = (s < SCTX) ? ctx[((size_t)b * SCTX + s) * CD + k0 + kk] : 0.f;
        }
        for (int i = tid; i < 64 * 16; i += 512) {
            int r = i >> 4, kk = i & 15;
            size_t gi = (size_t)(n0 + r) * CD + k0 + kk;
            wk_s [r][kk] = Wk [gi]; wv_s [r][kk] = Wv [gi];
            wki_s[r][kk] = Wki[gi]; wvi_s[r][kk] = Wvi[gi];
        }
        __syncthreads();
#pragma unroll
        for (int kk = 0; kk < 16; ++kk) {
            float wkv = wk_s[n][kk],  wvv = wv_s[n][kk];
            float wkiv = wki_s[n][kk], wviv = wvi_s[n][kk];
#pragma unroll
            for (int j = 0; j < 12; ++j) {
                int s = g * 12 + j;
                float c = cs[s][kk];
                bool txt = (s < eos);
                ak[j] = fmaf(c, txt ? wkv : wkiv, ak[j]);
                av[j] = fmaf(c, txt ? wvv : wviv, av[j]);
            }
        }
    }
    size_t base = ((size_t)(b * NH + hh) * SCTX) * DH + n;
#pragma unroll
    for (int j = 0; j < 12; ++j) {
        int s = g * 12 + j;
        if (s < SCTX) {
            g_k[base + (size_t)s * DH] = ak[j];
            g_v[base + (size_t)s * DH] = av[j];
        }
    }
}

// ---------------------------------------------------------------------------
// kv_pack: build swizzled fp16 K tiles and transposed Vt tiles per (b,h).
// ---------------------------------------------------------------------------
__global__ void __launch_bounds__(128) kv_pack(void)
{
    const int tid = threadIdx.x;
    const int bh  = blockIdx.x;

    for (int idx = tid; idx < 96 * 8; idx += 128) {
        int r = idx >> 3, cb = idx & 7;
        float4 u = {0,0,0,0}, v = {0,0,0,0};
        if (r < SCTX) {
            const float4* kp = (const float4*)(g_k + ((size_t)bh * SCTX + r) * DH + cb * 8);
            u = kp[0]; v = kp[1];
        }
        uint4 H;
        H.x = packhf(u.x, u.y); H.y = packhf(u.z, u.w);
        H.z = packhf(v.x, v.y); H.w = packhf(v.z, v.w);
        size_t off = (size_t)bh * 12288 + r * 128 + ((cb ^ (r & 7)) << 4);
        *(uint4*)(g_kt + off) = H;
    }
    for (int idx = tid; idx < 64 * 12; idx += 128) {
        int d = idx / 12, sc = idx % 12;
        float vals[8];
#pragma unroll
        for (int j = 0; j < 8; ++j) {
            int s = sc * 8 + j;
            vals[j] = (s < SCTX) ? g_v[((size_t)bh * SCTX + s) * DH + d] : 0.f;
        }
        uint4 H;
        H.x = packhf(vals[0], vals[1]); H.y = packhf(vals[2], vals[3]);
        H.z = packhf(vals[4], vals[5]); H.w = packhf(vals[6], vals[7]);
        size_t off = (size_t)bh * 13312 + d * 208 + sc * 16;
        *(uint4*)(g_vt + off) = H;
    }
}

// ---------------------------------------------------------------------------
// fp16 HMMA GEMM: C[m,n] = sum_k A[m,k]*B[n,k].
// 128x128 CTA tile, 8 warps (2m x 4n), K-chunk 32, 5-stage cp.async pipeline
// (loads issued 4 chunks ahead), 80KB smem -> 2 CTAs/SM.
// Rows 64B, swizzle: cb ^ ((r>>1)&3) on 16B columns.
// ---------------------------------------------------------------------------
#define GEMM_STAGES 5
#define TILE_BYTES  8192                  // 128 x 32 fp16
#define STAGE_BYTES (2 * TILE_BYTES)
#define GEMM_SMEM   (GEMM_STAGES * STAGE_BYTES)

__device__ __forceinline__ void load_tiles16(
    uint32_t sbase,
    const __half* __restrict__ A, const __half* __restrict__ B,
    int m0, int n0, int k0, int K, int tid)
{
#pragma unroll
    for (int i = 0; i < 4; ++i) {
        int idx = tid + (i << 8);            // 0..1023 16B chunks
        int mat = idx >> 9;                  // 0:A 1:B
        int w   = idx & 511;
        int r   = w >> 2;                    // 0..127
        int cb  = w & 3;                     // 16B column
        int grow = ((mat == 0) ? m0 : n0) + r;
        const __half* base = (mat == 0) ? A : B;
        const char* src = (const char*)(base + (size_t)grow * K + k0) + (cb << 4);
        uint32_t dst = sbase + (mat << 13) + (r << 6)
                     + (uint32_t)((cb ^ ((r >> 1) & 3)) << 4);
        CP_ASYNC16(dst, src);
    }
}

template <bool REMAP_Q, bool HAS_BIAS>
__global__ void __launch_bounds__(256, 2) gemm_fp16(
    const __half* __restrict__ A, const __half* __restrict__ B,
    const float* __restrict__ bias, float* __restrict__ C, int K)
{
    extern __shared__ __align__(128) char smem[];
    const uint32_t sb = smem_u32(smem);
    const int tid  = threadIdx.x;
    const int wid  = tid >> 5;
    const int lane = tid & 31;
    const int mw   = wid >> 2;
    const int nw   = wid & 3;
    const int n0   = blockIdx.x << 7;
    const int m0   = blockIdx.y << 7;
    const int NCH  = K >> 5;

    // per-thread fragment address components (64B rows)
    uint32_t aoff[4], axor[4];
#pragma unroll
    for (int mi = 0; mi < 4; ++mi) {
        uint32_t rA = (uint32_t)(mw * 64 + mi * 16 + (lane & 15));
        aoff[mi] = rA << 6;
        axor[mi] = (rA >> 1) & 3;
    }
    uint32_t boff[2], bxor[2];
#pragma unroll
    for (int bt = 0; bt < 2; ++bt) {
        uint32_t rB = (uint32_t)(nw * 32 + bt * 16 + ((lane >> 4) << 3)
                                 + (lane & 7));
        boff[bt] = rB << 6;
        bxor[bt] = (rB >> 1) & 3;
    }
    const uint32_t cA = (uint32_t)(lane >> 4);        // 0/1
    const uint32_t cB = (uint32_t)((lane >> 3) & 1);  // 0/1

    float acc[4][4][4];
#pragma unroll
    for (int i = 0; i < 4; ++i)
#pragma unroll
        for (int j = 0; j < 4; ++j)
#pragma unroll
            for (int v = 0; v < 4; ++v) acc[i][j][v] = 0.f;

    // prologue: fill 4 stages (loads run 4 chunks ahead)
#pragma unroll
    for (int c = 0; c < GEMM_STAGES - 1; ++c) {
        load_tiles16(sb + c * STAGE_BYTES, A, B, m0, n0, c << 5, K, tid);
        CP_COMMIT();
    }

    int s = 0;
    for (int c = 0; c < NCH; ++c) {
        CP_WAIT(3);
        __syncthreads();

        // prefetch chunk c+4 into the stage freed by chunk c-1
        if (c + GEMM_STAGES - 1 < NCH) {
            int sn = c + GEMM_STAGES - 1;
            load_tiles16(sb + (sn % GEMM_STAGES) * STAGE_BYTES, A, B,
                         m0, n0, sn << 5, K, tid);
        }
        CP_COMMIT();

        const uint32_t bA = sb + s * STAGE_BYTES;
        const uint32_t bB = bA + TILE_BYTES;

#pragma unroll
        for (int t = 0; t < 2; ++t) {
            const uint32_t cbA = (uint32_t)(2 * t) + cA;
            const uint32_t cbB = (uint32_t)(2 * t) + cB;

            uint32_t a[4][4], b[4][2];
#pragma unroll
            for (int mi = 0; mi < 4; ++mi) {
                uint32_t off = aoff[mi] + ((cbA ^ axor[mi]) << 4);
                ldsm_x4(bA + off, a[mi][0], a[mi][1], a[mi][2], a[mi][3]);
            }
#pragma unroll
            for (int bt = 0; bt < 2; ++bt) {
                uint32_t off = boff[bt] + ((cbB ^ bxor[bt]) << 4);
                ldsm_x4(bB + off, b[bt*2][0], b[bt*2][1],
                                  b[bt*2+1][0], b[bt*2+1][1]);
            }
#pragma unroll
            for (int mi = 0; mi < 4; ++mi)
#pragma unroll
                for (int ni = 0; ni < 4; ++ni)
                    mma_fp16(acc[mi][ni], a[mi], b[ni]);
        }
        s = (s == GEMM_STAGES - 1) ? 0 : s + 1;
    }

    // epilogue
#pragma unroll
    for (int mi = 0; mi < 4; ++mi) {
        const int mbase = m0 + mw * 64 + mi * 16 + (lane >> 2);
#pragma unroll
        for (int ni = 0; ni < 4; ++ni) {
            const int n = n0 + nw * 32 + ni * 8 + (lane & 3) * 2;
            if (REMAP_Q) {
                const int h = n >> 6, d = n & 63;
#pragma unroll
                for (int rr = 0; rr < 2; ++rr) {
                    const int m  = mbase + rr * 8;
                    const int b_ = m >> 12, sq = m & 4095;
                    const int qt = sq >> 7,  r  = sq & 127;
                    const int bh = b_ * NH + h;
                    size_t off = ((size_t)(bh * 32 + qt)) * 16384
                               + r * 128 + (((d >> 3) ^ (r & 7)) << 4)
                               + (d & 7) * 2;
                    *(uint32_t*)(g_qt + off) =
                        packhf(acc[mi][ni][rr * 2], acc[mi][ni][rr * 2 + 1]);
                }
            } else {
                float2 v0, v1;
                v0.x = acc[mi][ni][0]; v0.y = acc[mi][ni][1];
                v1.x = acc[mi][ni][2]; v1.y = acc[mi][ni][3];
                if (HAS_BIAS) {
                    float b0 = bias[n], b1 = bias[n + 1];
                    v0.x += b0; v0.y += b1; v1.x += b0; v1.y += b1;
                }
                *(float2*)(C + (size_t)mbase * QD + n) = v0;
                *(float2*)(C + (size_t)(mbase + 8) * QD + n) = v1;
            }
        }
    }
}

// ---------------------------------------------------------------------------
// fp16 single-pass flash-style two-segment attention (unchanged from R8).
// ---------------------------------------------------------------------------
#define AQ  0
#define AK  16384
#define AV  28672
#define ATTN_SMEM 41984

__global__ void __launch_bounds__(128) attn_mma(
    const float* __restrict__ scale_p, const int* __restrict__ nimg_p)
{
    extern __shared__ __align__(128) char smem[];
    const uint32_t sb = smem_u32(smem);
    const int tid  = threadIdx.x;
    const int lane = tid & 31;
    const int w    = tid >> 5;
    const int bh   = blockIdx.x;
    const int qt   = blockIdx.y;
    const int q0   = qt << 7;
    const int b    = bh / NH;
    const int h    = bh % NH;
    const int eos  = SCTX - *nimg_p;
    const float ipscale = *scale_p;

    {
        const unsigned char* qb = g_qt + ((size_t)(bh * 32 + qt)) * 16384;
        for (uint32_t o = tid * 16; o < 16384; o += 2048)
            CP_ASYNC16(sb + AQ + o, qb + o);
        const unsigned char* kb = g_kt + (size_t)bh * 12288;
        for (uint32_t o = tid * 16; o < 12288; o += 2048)
            CP_ASYNC16(sb + AK + o, kb + o);
        const unsigned char* vb = g_vt + (size_t)bh * 13312;
        for (uint32_t o = tid * 16; o < 13312; o += 2048)
            CP_ASYNC16(sb + AV + o, vb + o);
    }
    CP_COMMIT();
    CP_WAIT(0);
    __syncthreads();

    float Lg[2][12][4];
#pragma unroll
    for (int mi = 0; mi < 2; ++mi)
#pragma unroll
        for (int j = 0; j < 12; ++j)
#pragma unroll
            for (int v = 0; v < 4; ++v) Lg[mi][j][v] = 0.f;

#pragma unroll
    for (int kc = 0; kc < 4; ++kc) {
        uint32_t qa[2][4];
#pragma unroll
        for (int mi = 0; mi < 2; ++mi) {
            uint32_t row = (uint32_t)(w * 32 + mi * 16 + (lane & 15));
            uint32_t byte = row * 128
                + (((uint32_t)(kc * 32) + ((uint32_t)(lane >> 4) << 4))
                   ^ ((row & 7) << 4));
            ldsm_x4(sb + AQ + byte, qa[mi][0], qa[mi][1], qa[mi][2], qa[mi][3]);
        }
        uint32_t kb[12][2];
#pragma unroll
        for (int bt = 0; bt < 6; ++bt) {
            uint32_t row = (uint32_t)(bt * 16 + ((lane >> 4) << 3) + (lane & 7));
            uint32_t byte = row * 128
                + (((uint32_t)(kc * 32) + (((uint32_t)(lane >> 3) & 1) << 4))
                   ^ ((row & 7) << 4));
            ldsm_x4(sb + AK + byte, kb[bt*2][0], kb[bt*2][1],
                                    kb[bt*2+1][0], kb[bt*2+1][1]);
        }
#pragma unroll
        for (int mi = 0; mi < 2; ++mi)
#pragma unroll
            for (int j = 0; j < 12; ++j)
                mma_fp16(Lg[mi][j], qa[mi], kb[j]);
    }

    const int c0 = 2 * (lane & 3);
#pragma unroll
    for (int mi = 0; mi < 2; ++mi) {
#pragma unroll
        for (int half = 0; half < 2; ++half) {
            float mx1 = -1e30f, mx2 = -1e30f;
#pragma unroll
            for (int j = 0; j < 12; ++j)
#pragma unroll
                for (int u = 0; u < 2; ++u) {
                    int col = j * 8 + c0 + u;
                    float v = Lg[mi][j][half * 2 + u] * 0.125f;
                    Lg[mi][j][half * 2 + u] = v;
                    if (col < SCTX) {
                        if (col < eos) mx1 = fmaxf(mx1, v);
                        else           mx2 = fmaxf(mx2, v);
                    }
                }
            mx1 = fmaxf(mx1, __shfl_xor_sync(0xffffffffu, mx1, 1));
            mx1 = fmaxf(mx1, __shfl_xor_sync(0xffffffffu, mx1, 2));
            mx2 = fmaxf(mx2, __shfl_xor_sync(0xffffffffu, mx2, 1));
            mx2 = fmaxf(mx2, __shfl_xor_sync(0xffffffffu, mx2, 2));
            float s1 = 0.f, s2 = 0.f;
#pragma unroll
            for (int j = 0; j < 12; ++j)
#pragma unroll
                for (int u = 0; u < 2; ++u) {
                    int col = j * 8 + c0 + u;
                    float v = Lg[mi][j][half * 2 + u];
                    if (col < SCTX) {
                        if (col < eos) s1 += __expf(v - mx1);
                        else           s2 += __expf(v - mx2);
                    }
                }
            s1 += __shfl_xor_sync(0xffffffffu, s1, 1);
            s1 += __shfl_xor_sync(0xffffffffu, s1, 2);
            s2 += __shfl_xor_sync(0xffffffffu, s2, 1);
            s2 += __shfl_xor_sync(0xffffffffu, s2, 2);
            float w1 = (s1 > 0.f) ? 1.f / s1 : 0.f;
            float w2 = (s2 > 0.f) ? ipscale / s2 : 0.f;
#pragma unroll
            for (int j = 0; j < 12; ++j)
#pragma unroll
                for (int u = 0; u < 2; ++u) {
                    int col = j * 8 + c0 + u;
                    float v = Lg[mi][j][half * 2 + u];
                    float p = 0.f;
                    if (col < SCTX)
                        p = (col < eos) ? __expf(v - mx1) * w1
                                        : __expf(v - mx2) * w2;
                    Lg[mi][j][half * 2 + u] = p;
                }
        }
    }

    float o[2][8][4];
#pragma unroll
    for (int mi = 0; mi < 2; ++mi)
#pragma unroll
        for (int nd = 0; nd < 8; ++nd)
#pragma unroll
            for (int v = 0; v < 4; ++v) o[mi][nd][v] = 0.f;

#pragma unroll
    for (int kc = 0; kc < 6; ++kc) {
        uint32_t vb[8][2];
#pragma unroll
        for (int dt = 0; dt < 4; ++dt) {
            uint32_t row = (uint32_t)(dt * 16 + ((lane >> 4) << 3) + (lane & 7));
            uint32_t byte = row * 208 + (uint32_t)(kc * 32)
                          + (((uint32_t)(lane >> 3) & 1) << 4);
            ldsm_x4(sb + AV + byte, vb[dt*2][0], vb[dt*2][1],
                                    vb[dt*2+1][0], vb[dt*2+1][1]);
        }
#pragma unroll
        for (int mi = 0; mi < 2; ++mi) {
            const float* p0 = Lg[mi][2 * kc];
            const float* p1 = Lg[mi][2 * kc + 1];
            uint32_t pa[4];
            pa[0] = packhf(p0[0], p0[1]);
            pa[1] = packhf(p0[2], p0[3]);
            pa[2] = packhf(p1[0], p1[1]);
            pa[3] = packhf(p1[2], p1[3]);
#pragma unroll
            for (int nd = 0; nd < 8; ++nd)
                mma_fp16(o[mi][nd], pa, vb[nd]);
        }
    }

#pragma unroll
    for (int mi = 0; mi < 2; ++mi) {
        const int r0 = q0 + w * 32 + mi * 16 + (lane >> 2);
#pragma unroll
        for (int nd = 0; nd < 8; ++nd) {
            const int d = nd * 8 + c0;
            size_t base0 = ((size_t)b * SQ + r0) * INNER + h * DH + d;
            size_t base1 = base0 + (size_t)8 * INNER;
            *(uint32_t*)(g_a16 + base0) = packhf(o[mi][nd][0], o[mi][nd][1]);
            *(uint32_t*)(g_a16 + base1) = packhf(o[mi][nd][2], o[mi][nd][3]);
        }
    }
}

// ---------------------------------------------------------------------------
// Launch: x, context, scale, num_img_token, Wq, Wk, Wv, Wk_ip, Wv_ip, Wout, b_out
// ---------------------------------------------------------------------------
extern "C" void kernel_launch(void* const* d_in, const int* in_sizes, int n_in,
                              void* d_out, int out_size)
{
    const float* x     = (const float*)d_in[0];
    const float* ctx   = (const float*)d_in[1];
    const float* scale = (const float*)d_in[2];
    const int*   nimg  = (const int*)  d_in[3];
    const float* Wq    = (const float*)d_in[4];
    const float* Wout  = (const float*)d_in[9];
    const float* bout  = (const float*)d_in[10];
    float*       out   = (float*)d_out;

    __half *x16, *a16, *wq16, *wo16;
    cudaGetSymbolAddress((void**)&x16,  g_x16);
    cudaGetSymbolAddress((void**)&a16,  g_a16);
    cudaGetSymbolAddress((void**)&wq16, g_wq16);
    cudaGetSymbolAddress((void**)&wo16, g_wo16);

    cudaFuncSetAttribute(attn_mma,
        cudaFuncAttributeMaxDynamicSharedMemorySize, ATTN_SMEM);
    cudaFuncSetAttribute(gemm_fp16<true, false>,
        cudaFuncAttributeMaxDynamicSharedMemorySize, GEMM_SMEM);
    cudaFuncSetAttribute(gemm_fp16<false, true>,
        cudaFuncAttributeMaxDynamicSharedMemorySize, GEMM_SMEM);

    // conversions
    to_fp16<<<4096, 256>>>((const float4*)x, (ushort4*)x16,
                           (int)((size_t)BB * SQ * QD / 4));
    to_fp16<<<1600, 256>>>((const float4*)Wq, (ushort4*)wq16, INNER * QD / 4);
    to_fp16<<<1600, 256>>>((const float4*)Wout, (ushort4*)wo16, QD * INNER / 4);

    // K/V projections + packing into attention-ready fp16 tiles
    kv_proj_kernel<<<dim3(NH, BB), 512>>>(ctx,
        (const float*)d_in[5], (const float*)d_in[6],
        (const float*)d_in[7], (const float*)d_in[8], nimg);
    kv_pack<<<BB * NH, 128>>>();

    // Q projection (fp16 HMMA) -> swizzled fp16 Q tiles
    gemm_fp16<true, false><<<dim3(INNER / 128, (BB * SQ) / 128), 256, GEMM_SMEM>>>(
        x16, wq16, nullptr, nullptr, QD);

    // fp16 single-pass flash attention -> fp16
    attn_mma<<<dim3(BB * NH, SQ / 128), 128, ATTN_SMEM>>>(scale, nimg);

    // output projection + bias (fp16 HMMA)
    gemm_fp16<false, true><<<dim3(QD / 128, (BB * SQ) / 128), 256, GEMM_SMEM>>>(
        a16, wo16, bout, out, INNER);
}